// round 1
// baseline (speedup 1.0000x reference)
#include <cuda_runtime.h>
#include <cstdint>

// Problem constants (fixed by the dataset)
#define N_PTS   300000
#define INC     128
#define BATCH   4
#define GXD     50
#define GYD     50
#define GZD     4
#define NCELLS  40000          // BATCH*GXD*GYD*GZD
#define NCH     257            // 2*INC + 1 (cos | sin | count)

// Scratch (static device globals — no allocation allowed)
__device__ float g_grid[NCELLS * NCH];      // scatter target, zeroed each launch
__device__ float g_tmp [NCELLS * NCH];      // y/z box-summed grid
__device__ float g_agg [NCELLS * 2 * INC];  // final per-cell averages

// sin/cos with explicit range reduction: |pw| <~ 35, reduce into [-pi, pi]
// so even __sinf/__cosf (fast-math) stay accurate. Same helper used in both
// the scatter and gather kernels -> identical trig values.
__device__ __forceinline__ void sincos_red(float x, float* s, float* c) {
    float r = x - 6.283185307179586f * rintf(x * 0.15915494309189535f);
    *s = sinf(r);
    *c = cosf(r);
}

// ---------------------------------------------------------------------------
// K0: zero the scatter grid (NCELLS*NCH = 10,280,000 floats, /4 vectorized)
// ---------------------------------------------------------------------------
__global__ void k_zero() {
    int i = blockIdx.x * blockDim.x + threadIdx.x;
    if (i < (NCELLS * NCH) / 4) {
        reinterpret_cast<float4*>(g_grid)[i] = make_float4(0.f, 0.f, 0.f, 0.f);
    }
}

// ---------------------------------------------------------------------------
// K1: fused  h = LayerNorm(x @ W_mix^T),  pw = coords*W_pos, sincos,
//     atomic scatter of [h*cos | h*sin | 1] into g_grid[vid].
//
// Tile: BM=64 points x 128 out-channels, K=128. 256 threads.
// W (transposed) and x-tile (transposed) staged fully in smem; register
// micro-tile 4x8 per thread with float4 smem loads.
// ---------------------------------------------------------------------------
#define BM      64
#define WS_STR  132   // Ws[k][j], pad to mult-of-4, odd-bank stride
#define AS_STR  68    // As[k][r]
#define HS_STR  130   // Hs[r][c] (reuses As region)
#define SMEM_FLOATS (128 * WS_STR + 128 * AS_STR + 3 * INC)

__global__ void __launch_bounds__(256)
k_gemm_ln_scatter(const float* __restrict__ x,
                  const int*   __restrict__ coords,
                  const float* __restrict__ Wm,
                  const float* __restrict__ gamma,
                  const float* __restrict__ beta,
                  const float* __restrict__ Wp)
{
    extern __shared__ float sm[];
    float* Ws  = sm;                       // [128][WS_STR]: Ws[k][j] = Wm[j][k]
    float* As  = sm + 128 * WS_STR;        // [128][AS_STR]: As[k][r] = x[row0+r][k]
    float* Wps = As + 128 * AS_STR;        // [3*INC]

    const int tid  = threadIdx.x;
    const int row0 = blockIdx.x * BM;

    // Stage W transposed (coalesced gmem read, strided smem write)
    #pragma unroll 4
    for (int idx = tid; idx < 128 * 128; idx += 256) {
        int j = idx >> 7, k = idx & 127;
        Ws[k * WS_STR + j] = Wm[idx];
    }
    // Stage x tile transposed, zero-pad OOB rows
    #pragma unroll 4
    for (int idx = tid; idx < BM * 128; idx += 256) {
        int r = idx >> 7, k = idx & 127;
        int gr = row0 + r;
        As[k * AS_STR + r] = (gr < N_PTS) ? x[(size_t)gr * INC + k] : 0.0f;
    }
    for (int idx = tid; idx < 3 * INC; idx += 256) Wps[idx] = Wp[idx];
    __syncthreads();

    // GEMM: thread (tr,tc) in 16x16 grid computes rows tr*4..+3, cols tc*8..+7
    const int tr = tid >> 4;
    const int tc = tid & 15;
    float acc[4][8];
    #pragma unroll
    for (int m = 0; m < 4; m++)
        #pragma unroll
        for (int u = 0; u < 8; u++) acc[m][u] = 0.0f;

    #pragma unroll 8
    for (int k = 0; k < 128; k++) {
        float4 a  = *reinterpret_cast<const float4*>(&As[k * AS_STR + tr * 4]);
        float4 b0 = *reinterpret_cast<const float4*>(&Ws[k * WS_STR + tc * 8]);
        float4 b1 = *reinterpret_cast<const float4*>(&Ws[k * WS_STR + tc * 8 + 4]);
        float av[4] = {a.x, a.y, a.z, a.w};
        float bv[8] = {b0.x, b0.y, b0.z, b0.w, b1.x, b1.y, b1.z, b1.w};
        #pragma unroll
        for (int m = 0; m < 4; m++)
            #pragma unroll
            for (int u = 0; u < 8; u++)
                acc[m][u] = fmaf(av[m], bv[u], acc[m][u]);
    }
    __syncthreads();   // done reading As before overwriting it as Hs

    // Park h tile in smem (reuse As region) for row-wise LayerNorm
    float* Hs = As;    // [BM][HS_STR], 64*130 = 8320 <= 128*68 = 8704 floats
    #pragma unroll
    for (int m = 0; m < 4; m++)
        #pragma unroll
        for (int u = 0; u < 8; u++)
            Hs[(tr * 4 + m) * HS_STR + tc * 8 + u] = acc[m][u];
    __syncthreads();

    // LN + positional sincos + atomic scatter: each warp owns 8 rows
    const int warp = tid >> 5, lane = tid & 31;
    #pragma unroll 1
    for (int i = 0; i < 8; i++) {
        int r  = warp * 8 + i;
        int gr = row0 + r;
        if (gr >= N_PTS) break;   // uniform within warp

        float v[4];
        float s = 0.f, ssq = 0.f;
        #pragma unroll
        for (int q = 0; q < 4; q++) {
            v[q] = Hs[r * HS_STR + lane + 32 * q];
            s += v[q];
            ssq += v[q] * v[q];
        }
        #pragma unroll
        for (int off = 16; off; off >>= 1) {
            s   += __shfl_xor_sync(0xffffffffu, s, off);
            ssq += __shfl_xor_sync(0xffffffffu, ssq, off);
        }
        float mu  = s * (1.0f / 128.0f);
        float var = ssq * (1.0f / 128.0f) - mu * mu;
        float rs  = rsqrtf(var + 1e-6f);

        int4 cd = *reinterpret_cast<const int4*>(&coords[(size_t)gr * 4]);
        float fx = (float)cd.x, fy = (float)cd.y, fz = (float)cd.z;
        int vid = ((cd.w * GXD + (cd.x >> 3)) * GYD + (cd.y >> 3)) * GZD + (cd.z >> 3);
        float* gc = g_grid + (size_t)vid * NCH;

        #pragma unroll
        for (int q = 0; q < 4; q++) {
            int c = lane + 32 * q;
            float hn = (v[q] - mu) * rs * gamma[c] + beta[c];
            float pw = fx * Wps[c] + fy * Wps[INC + c] + fz * Wps[2 * INC + c];
            float sn, cs;
            sincos_red(pw, &sn, &cs);
            atomicAdd(gc + c,       hn * cs);
            atomicAdd(gc + INC + c, hn * sn);
        }
        if (lane == 0) atomicAdd(gc + 2 * INC, 1.0f);
    }
}

// ---------------------------------------------------------------------------
// K2a: 9-point box sum over (y,z) with zero padding. One block per cell.
// Neighbor cell offset: dy*GZD + dz (same b, same x).
// ---------------------------------------------------------------------------
__global__ void k_box_yz() {
    int cell = blockIdx.x;
    int rem  = cell % (GYD * GZD);
    int cy   = rem / GZD;
    int cz   = rem % GZD;
    int dylo = (cy > 0) ? -1 : 0, dyhi = (cy < GYD - 1) ? 1 : 0;
    int dzlo = (cz > 0) ? -1 : 0, dzhi = (cz < GZD - 1) ? 1 : 0;

    for (int ch = threadIdx.x; ch < NCH; ch += 256) {
        float s = 0.f;
        for (int dy = dylo; dy <= dyhi; dy++)
            for (int dz = dzlo; dz <= dzhi; dz++)
                s += g_grid[(size_t)(cell + dy * GZD + dz) * NCH + ch];
        g_tmp[(size_t)cell * NCH + ch] = s;
    }
}

// ---------------------------------------------------------------------------
// K2b: 3-point sum over x + divide by count -> g_agg[cell][0..255].
// ---------------------------------------------------------------------------
__global__ void k_box_x_div() {
    int cell = blockIdx.x;
    int cx   = (cell % (GXD * GYD * GZD)) / (GYD * GZD);
    int c    = threadIdx.x;   // 0..255

    float num = 0.f, den = 0.f;
    #pragma unroll
    for (int dx = -1; dx <= 1; dx++) {
        int xx = cx + dx;
        if (xx < 0 || xx >= GXD) continue;
        const float* p = g_tmp + (size_t)(cell + dx * GYD * GZD) * NCH;
        num += p[c];
        den += p[2 * INC];    // broadcast load
    }
    g_agg[(size_t)cell * (2 * INC) + c] = num / fmaxf(den, 1e-12f);
}

// ---------------------------------------------------------------------------
// K3: gather + recombine: out[i][c] = agg[vid][c]*cos + agg[vid][c+128]*sin
// ---------------------------------------------------------------------------
__global__ void k_gather(const int* __restrict__ coords,
                         const float* __restrict__ Wp,
                         float* __restrict__ out)
{
    int t = blockIdx.x * blockDim.x + threadIdx.x;
    if (t >= N_PTS * INC) return;
    int i = t >> 7;
    int c = t & 127;

    int4 cd = *reinterpret_cast<const int4*>(&coords[(size_t)i * 4]);
    int vid = ((cd.w * GXD + (cd.x >> 3)) * GYD + (cd.y >> 3)) * GZD + (cd.z >> 3);

    float pw = (float)cd.x * Wp[c] + (float)cd.y * Wp[INC + c] + (float)cd.z * Wp[2 * INC + c];
    float sn, cs;
    sincos_red(pw, &sn, &cs);

    const float* a = g_agg + (size_t)vid * (2 * INC);
    out[t] = a[c] * cs + a[c + INC] * sn;
}

// ---------------------------------------------------------------------------
// Launch
// ---------------------------------------------------------------------------
extern "C" void kernel_launch(void* const* d_in, const int* in_sizes, int n_in,
                              void* d_out, int out_size)
{
    const float* x      = (const float*)d_in[0];
    const int*   coords = (const int*)  d_in[1];
    const float* Wm     = (const float*)d_in[2];
    const float* gamma  = (const float*)d_in[3];
    const float* beta   = (const float*)d_in[4];
    const float* Wp     = (const float*)d_in[5];
    // d_in[6] = stride (== 8, hardcoded)
    float* out = (float*)d_out;

    const int smem_bytes = SMEM_FLOATS * (int)sizeof(float);   // ~104 KB
    cudaFuncSetAttribute(k_gemm_ln_scatter,
                         cudaFuncAttributeMaxDynamicSharedMemorySize, smem_bytes);

    k_zero<<<((NCELLS * NCH) / 4 + 255) / 256, 256>>>();
    k_gemm_ln_scatter<<<(N_PTS + BM - 1) / BM, 256, smem_bytes>>>(
        x, coords, Wm, gamma, beta, Wp);
    k_box_yz<<<NCELLS, 256>>>();
    k_box_x_div<<<NCELLS, 256>>>();
    k_gather<<<(N_PTS * INC + 255) / 256, 256>>>(coords, Wp, out);
}

// round 4
// speedup vs baseline: 1.5146x; 1.5146x over previous
#include <cuda_runtime.h>
#include <cuda_fp16.h>
#include <cstdint>

// Problem constants (fixed by the dataset)
#define N_PTS   300000
#define INC     128
#define BATCH   4
#define GXD     50
#define GYD     50
#define GZD     4
#define NCELLS  40000          // BATCH*GXD*GYD*GZD
#define NCH     257            // 2*INC + 1 (cos | sin | count)

// Scratch (static device globals — no allocation allowed)
__device__ float g_grid[NCELLS * NCH];      // scatter target, zeroed each launch
__device__ float g_tmp [NCELLS * NCH];      // y/z box-summed grid
__device__ float g_agg [NCELLS * 2 * INC];  // final per-cell averages

// sin/cos: explicit range reduction into [-pi, pi], then HW MUFU intrinsics.
// |pw| <~ 35 so one fma-reduction step is exact enough; __sinf/__cosf abs err
// ~2^-21 on the reduced range — far under the 1e-3 threshold.
__device__ __forceinline__ void sincos_red(float x, float* s, float* c) {
    float r = x - 6.283185307179586f * rintf(x * 0.15915494309189535f);
    *s = __sinf(r);
    *c = __cosf(r);
}

// ---------------------------------------------------------------------------
// K0: zero the scatter grid
// ---------------------------------------------------------------------------
__global__ void k_zero() {
    int i = blockIdx.x * blockDim.x + threadIdx.x;
    if (i < (NCELLS * NCH) / 4) {
        reinterpret_cast<float4*>(g_grid)[i] = make_float4(0.f, 0.f, 0.f, 0.f);
    }
}

// ---------------------------------------------------------------------------
// K1: mma.sync fp16x3-split GEMM (h = x @ Wm^T) + per-row LayerNorm +
//     sincos + coalesced atomic scatter. 256 threads, 128 points/block.
// ---------------------------------------------------------------------------
#define LDA   136                       // halves per smem row (8-half pad)
#define TILE_HALF_BYTES (128 * LDA * 2) // 34816 B per fp16 tile

#define OFF_A_HI  0
#define OFF_A_LO  (OFF_A_HI + TILE_HALF_BYTES)
#define OFF_B_HI  (OFF_A_LO + TILE_HALF_BYTES)
#define OFF_B_LO  (OFF_B_HI + TILE_HALF_BYTES)   // operands end at 139264
#define OFF_COORD (OFF_B_LO + TILE_HALF_BYTES)   // int4[128]  = 2048
#define OFF_VID   (OFF_COORD + 2048)             // int[128]   = 512
#define OFF_GAMMA (OFF_VID + 512)
#define OFF_BETA  (OFF_GAMMA + 512)
#define OFF_WP    (OFF_BETA + 512)               // float[384] = 1536
#define SMEM_BYTES (OFF_WP + 1536)               // 144384

// F staging (reuses operand region after mainloop): Hs[p][256] rotate-swizzled
#define OFF_HS    0                              // 128*256*4 = 131072 <= 139264

__device__ __forceinline__ void mma16816(float* c,
                                         uint32_t a0, uint32_t a1,
                                         uint32_t a2, uint32_t a3,
                                         uint32_t b0, uint32_t b1) {
    asm volatile(
        "mma.sync.aligned.m16n8k16.row.col.f32.f16.f16.f32 "
        "{%0,%1,%2,%3}, {%4,%5,%6,%7}, {%8,%9}, {%0,%1,%2,%3};"
        : "+f"(c[0]), "+f"(c[1]), "+f"(c[2]), "+f"(c[3])
        : "r"(a0), "r"(a1), "r"(a2), "r"(a3), "r"(b0), "r"(b1));
}

// split (v0,v1) into packed half2 hi + half2 lo
__device__ __forceinline__ void cvt_split(float v0, float v1,
                                          uint32_t& hi, uint32_t& lo) {
    __half h0 = __float2half_rn(v0);
    __half h1 = __float2half_rn(v1);
    __half l0 = __float2half_rn(v0 - __half2float(h0));
    __half l1 = __float2half_rn(v1 - __half2float(h1));
    hi = ((uint32_t)__half_as_ushort(h1) << 16) | __half_as_ushort(h0);
    lo = ((uint32_t)__half_as_ushort(l1) << 16) | __half_as_ushort(l0);
}

__global__ void __launch_bounds__(256)
k_gemm_ln_scatter(const float* __restrict__ x,
                  const int*   __restrict__ coords,
                  const float* __restrict__ Wm,
                  const float* __restrict__ gamma,
                  const float* __restrict__ beta,
                  const float* __restrict__ Wp)
{
    extern __shared__ char smraw[];
    __half* AsHi = (__half*)(smraw + OFF_A_HI);
    __half* AsLo = (__half*)(smraw + OFF_A_LO);
    __half* BsHi = (__half*)(smraw + OFF_B_HI);
    __half* BsLo = (__half*)(smraw + OFF_B_LO);
    int4*   sCd  = (int4*)  (smraw + OFF_COORD);
    int*    sVid = (int*)   (smraw + OFF_VID);
    float*  sGa  = (float*) (smraw + OFF_GAMMA);
    float*  sBe  = (float*) (smraw + OFF_BETA);
    float*  sWp  = (float*) (smraw + OFF_WP);
    float*  Hs   = (float*) (smraw + OFF_HS);

    const int tid  = threadIdx.x;
    const int row0 = blockIdx.x * 128;

    // ---- Stage operands: 2 threads per row, each does 64 cols (16 float4) ----
    {
        int row = tid >> 1, sel = tid & 1;
        // W: Bs[n=row][k]
        const float4* wrow = (const float4*)(Wm + (size_t)row * 128) + sel * 16;
        #pragma unroll
        for (int q = 0; q < 16; q++) {
            float4 v = wrow[q];
            int c = sel * 64 + q * 4;
            uint32_t hi, lo;
            cvt_split(v.x, v.y, hi, lo);
            *(uint32_t*)(BsHi + row * LDA + c)     = hi;
            *(uint32_t*)(BsLo + row * LDA + c)     = lo;
            cvt_split(v.z, v.w, hi, lo);
            *(uint32_t*)(BsHi + row * LDA + c + 2) = hi;
            *(uint32_t*)(BsLo + row * LDA + c + 2) = lo;
        }
        // x: As[m=row][k], zero-pad OOB rows
        int gr = row0 + row;
        if (gr < N_PTS) {
            const float4* xrow = (const float4*)(x + (size_t)gr * 128) + sel * 16;
            #pragma unroll
            for (int q = 0; q < 16; q++) {
                float4 v = xrow[q];
                int c = sel * 64 + q * 4;
                uint32_t hi, lo;
                cvt_split(v.x, v.y, hi, lo);
                *(uint32_t*)(AsHi + row * LDA + c)     = hi;
                *(uint32_t*)(AsLo + row * LDA + c)     = lo;
                cvt_split(v.z, v.w, hi, lo);
                *(uint32_t*)(AsHi + row * LDA + c + 2) = hi;
                *(uint32_t*)(AsLo + row * LDA + c + 2) = lo;
            }
        } else {
            #pragma unroll
            for (int q = 0; q < 16; q++) {
                int c = sel * 64 + q * 4;
                *(uint32_t*)(AsHi + row * LDA + c)     = 0u;
                *(uint32_t*)(AsLo + row * LDA + c)     = 0u;
                *(uint32_t*)(AsHi + row * LDA + c + 2) = 0u;
                *(uint32_t*)(AsLo + row * LDA + c + 2) = 0u;
            }
        }
    }
    // Small params + coords + vid
    if (tid < 128) {
        sGa[tid] = gamma[tid];
        sBe[tid] = beta[tid];
        #pragma unroll
        for (int q = 0; q < 3; q++) sWp[q * 128 + tid] = Wp[q * 128 + tid];
        int gr = row0 + tid;
        int4 cd = (gr < N_PTS) ? *reinterpret_cast<const int4*>(&coords[(size_t)gr * 4])
                               : make_int4(0, 0, 0, 0);
        sCd[tid]  = cd;
        sVid[tid] = ((cd.w * GXD + (cd.x >> 3)) * GYD + (cd.y >> 3)) * GZD + (cd.z >> 3);
    }
    __syncthreads();

    // ---- Warp-tiled mainloop: warp w owns rows [w*16, w*16+16), all 128 cols ----
    const int w    = tid >> 5;
    const int lane = tid & 31;
    const int g    = lane >> 2;      // groupID
    const int t    = lane & 3;       // thread-in-group
    const int w16  = w * 16;

    float acc[16][4];
    #pragma unroll
    for (int nt = 0; nt < 16; nt++)
        #pragma unroll
        for (int j = 0; j < 4; j++) acc[nt][j] = 0.f;

    #pragma unroll 1
    for (int pass = 0; pass < 3; pass++) {
        const __half* Ap = (pass == 1) ? AsLo : AsHi;
        const __half* Bp = (pass == 2) ? BsLo : BsHi;
        #pragma unroll 1
        for (int k16 = 0; k16 < 8; k16++) {
            const int kk = k16 * 16 + 2 * t;
            uint32_t a0 = *(const uint32_t*)(Ap + (w16 + g)     * LDA + kk);
            uint32_t a1 = *(const uint32_t*)(Ap + (w16 + g + 8) * LDA + kk);
            uint32_t a2 = *(const uint32_t*)(Ap + (w16 + g)     * LDA + kk + 8);
            uint32_t a3 = *(const uint32_t*)(Ap + (w16 + g + 8) * LDA + kk + 8);
            #pragma unroll
            for (int nt = 0; nt < 16; nt++) {
                uint32_t b0 = *(const uint32_t*)(Bp + (nt * 8 + g) * LDA + kk);
                uint32_t b1 = *(const uint32_t*)(Bp + (nt * 8 + g) * LDA + kk + 8);
                mma16816(acc[nt], a0, a1, a2, a3, b0, b1);
            }
        }
    }
    __syncthreads();   // all warps done reading operands; Hs may overwrite them

    // ---- LayerNorm stats: rows r0 = w16+g, r1 = r0+8 ----
    float s0 = 0.f, q0 = 0.f, s1 = 0.f, q1 = 0.f;
    #pragma unroll
    for (int nt = 0; nt < 16; nt++) {
        s0 += acc[nt][0] + acc[nt][1];
        q0 += acc[nt][0] * acc[nt][0] + acc[nt][1] * acc[nt][1];
        s1 += acc[nt][2] + acc[nt][3];
        q1 += acc[nt][2] * acc[nt][2] + acc[nt][3] * acc[nt][3];
    }
    #pragma unroll
    for (int off = 1; off <= 2; off <<= 1) {
        s0 += __shfl_xor_sync(0xffffffffu, s0, off);
        q0 += __shfl_xor_sync(0xffffffffu, q0, off);
        s1 += __shfl_xor_sync(0xffffffffu, s1, off);
        q1 += __shfl_xor_sync(0xffffffffu, q1, off);
    }
    float mu0 = s0 * (1.f / 128.f), var0 = q0 * (1.f / 128.f) - mu0 * mu0;
    float mu1 = s1 * (1.f / 128.f), var1 = q1 * (1.f / 128.f) - mu1 * mu1;
    float rs0 = rsqrtf(var0 + 1e-6f);
    float rs1 = rsqrtf(var1 + 1e-6f);

    const int r0l = w16 + g, r1l = r0l + 8;
    int4 cd0 = sCd[r0l], cd1 = sCd[r1l];
    float fx0 = (float)cd0.x, fy0 = (float)cd0.y, fz0 = (float)cd0.z;
    float fx1 = (float)cd1.x, fy1 = (float)cd1.y, fz1 = (float)cd1.z;

    // ---- F = [h*cos | h*sin] into rotate-swizzled smem ----
    #pragma unroll
    for (int nt = 0; nt < 16; nt++) {
        #pragma unroll
        for (int j = 0; j < 2; j++) {
            int c = nt * 8 + 2 * t + j;
            float ga = sGa[c], be = sBe[c];
            float w0 = sWp[c], w1 = sWp[128 + c], w2 = sWp[256 + c];
            {
                float hn = (acc[nt][j] - mu0) * rs0 * ga + be;
                float sn, cs;
                sincos_red(fx0 * w0 + fy0 * w1 + fz0 * w2, &sn, &cs);
                Hs[r0l * 256 + ((c + r0l) & 255)]       = hn * cs;
                Hs[r0l * 256 + ((c + 128 + r0l) & 255)] = hn * sn;
            }
            {
                float hn = (acc[nt][2 + j] - mu1) * rs1 * ga + be;
                float sn, cs;
                sincos_red(fx1 * w0 + fy1 * w1 + fz1 * w2, &sn, &cs);
                Hs[r1l * 256 + ((c + r1l) & 255)]       = hn * cs;
                Hs[r1l * 256 + ((c + 128 + r1l) & 255)] = hn * sn;
            }
        }
    }
    // Count channel: one atomic per point
    if (tid < 128 && row0 + tid < N_PTS)
        atomicAdd(&g_grid[(size_t)sVid[tid] * NCH + 2 * INC], 1.0f);

    __syncthreads();

    // ---- Coalesced scatter: warp per point, lane = channel ----
    for (int i = 0; i < 16; i++) {
        int p  = w * 16 + i;
        int gp = row0 + p;
        if (gp >= N_PTS) break;          // warp-uniform
        float* gc = g_grid + (size_t)sVid[p] * NCH;
        #pragma unroll
        for (int q = 0; q < 4; q++) {
            int c = lane + 32 * q;
            atomicAdd(gc + c,       Hs[p * 256 + ((c + p) & 255)]);
            atomicAdd(gc + INC + c, Hs[p * 256 + ((c + 128 + p) & 255)]);
        }
    }
}

// ---------------------------------------------------------------------------
// K2a: 9-point box sum over (y,z) with zero padding. One block per cell.
// ---------------------------------------------------------------------------
__global__ void k_box_yz() {
    int cell = blockIdx.x;
    int rem  = cell % (GYD * GZD);
    int cy   = rem / GZD;
    int cz   = rem % GZD;
    int dylo = (cy > 0) ? -1 : 0, dyhi = (cy < GYD - 1) ? 1 : 0;
    int dzlo = (cz > 0) ? -1 : 0, dzhi = (cz < GZD - 1) ? 1 : 0;

    for (int ch = threadIdx.x; ch < NCH; ch += 256) {
        float sv = 0.f;
        for (int dy = dylo; dy <= dyhi; dy++)
            for (int dz = dzlo; dz <= dzhi; dz++)
                sv += g_grid[(size_t)(cell + dy * GZD + dz) * NCH + ch];
        g_tmp[(size_t)cell * NCH + ch] = sv;
    }
}

// ---------------------------------------------------------------------------
// K2b: 3-point sum over x + divide by count -> g_agg[cell][0..255].
// ---------------------------------------------------------------------------
__global__ void k_box_x_div() {
    int cell = blockIdx.x;
    int cx   = (cell % (GXD * GYD * GZD)) / (GYD * GZD);
    int c    = threadIdx.x;   // 0..255

    float num = 0.f, den = 0.f;
    #pragma unroll
    for (int dx = -1; dx <= 1; dx++) {
        int xx = cx + dx;
        if (xx < 0 || xx >= GXD) continue;
        const float* p = g_tmp + (size_t)(cell + dx * GYD * GZD) * NCH;
        num += p[c];
        den += p[2 * INC];
    }
    g_agg[(size_t)cell * (2 * INC) + c] = num / fmaxf(den, 1e-12f);
}

// ---------------------------------------------------------------------------
// K3: gather + recombine
// ---------------------------------------------------------------------------
__global__ void k_gather(const int* __restrict__ coords,
                         const float* __restrict__ Wp,
                         float* __restrict__ out)
{
    int t = blockIdx.x * blockDim.x + threadIdx.x;
    if (t >= N_PTS * INC) return;
    int i = t >> 7;
    int c = t & 127;

    int4 cd = *reinterpret_cast<const int4*>(&coords[(size_t)i * 4]);
    int vid = ((cd.w * GXD + (cd.x >> 3)) * GYD + (cd.y >> 3)) * GZD + (cd.z >> 3);

    float pw = (float)cd.x * Wp[c] + (float)cd.y * Wp[INC + c] + (float)cd.z * Wp[2 * INC + c];
    float sn, cs;
    sincos_red(pw, &sn, &cs);

    const float* a = g_agg + (size_t)vid * (2 * INC);
    out[t] = a[c] * cs + a[c + INC] * sn;
}

// ---------------------------------------------------------------------------
// Launch
// ---------------------------------------------------------------------------
extern "C" void kernel_launch(void* const* d_in, const int* in_sizes, int n_in,
                              void* d_out, int out_size)
{
    const float* x      = (const float*)d_in[0];
    const int*   coords = (const int*)  d_in[1];
    const float* Wm     = (const float*)d_in[2];
    const float* gamma  = (const float*)d_in[3];
    const float* beta   = (const float*)d_in[4];
    const float* Wp     = (const float*)d_in[5];
    float* out = (float*)d_out;

    cudaFuncSetAttribute(k_gemm_ln_scatter,
                         cudaFuncAttributeMaxDynamicSharedMemorySize, SMEM_BYTES);

    k_zero<<<((NCELLS * NCH) / 4 + 255) / 256, 256>>>();
    k_gemm_ln_scatter<<<(N_PTS + 127) / 128, 256, SMEM_BYTES>>>(
        x, coords, Wm, gamma, beta, Wp);
    k_box_yz<<<NCELLS, 256>>>();
    k_box_x_div<<<NCELLS, 256>>>();
    k_gather<<<(N_PTS * INC + 255) / 256, 256>>>(coords, Wp, out);
}

// round 5
// speedup vs baseline: 2.0684x; 1.3656x over previous
#include <cuda_runtime.h>
#include <cuda_fp16.h>
#include <cstdint>

// Problem constants (fixed by the dataset)
#define N_PTS   300000
#define INC     128
#define BATCH   4
#define GXD     50
#define GYD     50
#define GZD     4
#define NCELLS  40000          // BATCH*GXD*GYD*GZD
#define NFCH    256            // 2*INC feature channels (cos | sin)

// Scratch (static device globals — no allocation allowed)
__device__ float g_grid[NCELLS * NFCH];     // scatter target [cell][256]
__device__ float g_cnt [NCELLS];            // per-cell point count
__device__ float g_tmp [NCELLS * NFCH];     // y/z box-summed features
__device__ float g_tmpc[NCELLS];            // y/z box-summed counts
__device__ float g_agg [NCELLS * NFCH];     // final per-cell averages

// sin/cos: explicit range reduction into [-pi, pi], then HW MUFU intrinsics.
__device__ __forceinline__ void sincos_red(float x, float* s, float* c) {
    float r = x - 6.283185307179586f * rintf(x * 0.15915494309189535f);
    *s = __sinf(r);
    *c = __cosf(r);
}

// Vectorized float4 reduction (PTX ISA 8.1, sm_90+ base feature)
__device__ __forceinline__ void red_add_v4(float* p, float4 v) {
    asm volatile("red.global.add.v4.f32 [%0], {%1, %2, %3, %4};"
                 :: "l"(p), "f"(v.x), "f"(v.y), "f"(v.z), "f"(v.w) : "memory");
}

// ---------------------------------------------------------------------------
// K0: zero the scatter grid + counts
// ---------------------------------------------------------------------------
__global__ void k_zero() {
    int i = blockIdx.x * blockDim.x + threadIdx.x;
    float4 z = make_float4(0.f, 0.f, 0.f, 0.f);
    if (i < (NCELLS * NFCH) / 4) reinterpret_cast<float4*>(g_grid)[i] = z;
    if (i < NCELLS / 4)          reinterpret_cast<float4*>(g_cnt)[i]  = z;
}

// ---------------------------------------------------------------------------
// K1: mma.sync fp16x3-split GEMM (h = x @ Wm^T) + per-row LayerNorm +
//     sincos + float4 vectorized atomic scatter. 256 threads, 128 pts/block.
// ---------------------------------------------------------------------------
#define LDA   136                       // halves per smem row (8-half pad)
#define TILE_HALF_BYTES (128 * LDA * 2) // 34816 B per fp16 tile

#define OFF_A_HI  0
#define OFF_A_LO  (OFF_A_HI + TILE_HALF_BYTES)
#define OFF_B_HI  (OFF_A_LO + TILE_HALF_BYTES)
#define OFF_B_LO  (OFF_B_HI + TILE_HALF_BYTES)   // operands end at 139264
#define OFF_COORD (OFF_B_LO + TILE_HALF_BYTES)   // int4[128]  = 2048
#define OFF_VID   (OFF_COORD + 2048)             // int[128]   = 512
#define OFF_GAMMA (OFF_VID + 512)
#define OFF_BETA  (OFF_GAMMA + 512)
#define OFF_WP    (OFF_BETA + 512)               // float[384] = 1536
#define SMEM_BYTES (OFF_WP + 1536)               // 144384

// F staging (reuses operand region after mainloop):
// Hs4[p][phys4], phys4 = (c4 + p) & 63  (float4-granular rotation, p = 0..127)
#define OFF_HS    0                              // 128*64*16 = 131072 <= 139264

__device__ __forceinline__ void mma16816(float* c,
                                         uint32_t a0, uint32_t a1,
                                         uint32_t a2, uint32_t a3,
                                         uint32_t b0, uint32_t b1) {
    asm volatile(
        "mma.sync.aligned.m16n8k16.row.col.f32.f16.f16.f32 "
        "{%0,%1,%2,%3}, {%4,%5,%6,%7}, {%8,%9}, {%0,%1,%2,%3};"
        : "+f"(c[0]), "+f"(c[1]), "+f"(c[2]), "+f"(c[3])
        : "r"(a0), "r"(a1), "r"(a2), "r"(a3), "r"(b0), "r"(b1));
}

// split (v0,v1) into packed half2 hi + half2 lo
__device__ __forceinline__ void cvt_split(float v0, float v1,
                                          uint32_t& hi, uint32_t& lo) {
    __half h0 = __float2half_rn(v0);
    __half h1 = __float2half_rn(v1);
    __half l0 = __float2half_rn(v0 - __half2float(h0));
    __half l1 = __float2half_rn(v1 - __half2float(h1));
    hi = ((uint32_t)__half_as_ushort(h1) << 16) | __half_as_ushort(h0);
    lo = ((uint32_t)__half_as_ushort(l1) << 16) | __half_as_ushort(l0);
}

__global__ void __launch_bounds__(256)
k_gemm_ln_scatter(const float* __restrict__ x,
                  const int*   __restrict__ coords,
                  const float* __restrict__ Wm,
                  const float* __restrict__ gamma,
                  const float* __restrict__ beta,
                  const float* __restrict__ Wp)
{
    extern __shared__ char smraw[];
    __half* AsHi = (__half*)(smraw + OFF_A_HI);
    __half* AsLo = (__half*)(smraw + OFF_A_LO);
    __half* BsHi = (__half*)(smraw + OFF_B_HI);
    __half* BsLo = (__half*)(smraw + OFF_B_LO);
    int4*   sCd  = (int4*)  (smraw + OFF_COORD);
    int*    sVid = (int*)   (smraw + OFF_VID);
    float*  sGa  = (float*) (smraw + OFF_GAMMA);
    float*  sBe  = (float*) (smraw + OFF_BETA);
    float*  sWp  = (float*) (smraw + OFF_WP);
    float*  Hs   = (float*) (smraw + OFF_HS);
    float4* Hs4  = (float4*)(smraw + OFF_HS);

    const int tid  = threadIdx.x;
    const int row0 = blockIdx.x * 128;

    // ---- Stage operands: 2 threads per row, each does 64 cols (16 float4) ----
    {
        int row = tid >> 1, sel = tid & 1;
        const float4* wrow = (const float4*)(Wm + (size_t)row * 128) + sel * 16;
        #pragma unroll
        for (int q = 0; q < 16; q++) {
            float4 v = wrow[q];
            int c = sel * 64 + q * 4;
            uint32_t hi, lo;
            cvt_split(v.x, v.y, hi, lo);
            *(uint32_t*)(BsHi + row * LDA + c)     = hi;
            *(uint32_t*)(BsLo + row * LDA + c)     = lo;
            cvt_split(v.z, v.w, hi, lo);
            *(uint32_t*)(BsHi + row * LDA + c + 2) = hi;
            *(uint32_t*)(BsLo + row * LDA + c + 2) = lo;
        }
        int gr = row0 + row;
        if (gr < N_PTS) {
            const float4* xrow = (const float4*)(x + (size_t)gr * 128) + sel * 16;
            #pragma unroll
            for (int q = 0; q < 16; q++) {
                float4 v = xrow[q];
                int c = sel * 64 + q * 4;
                uint32_t hi, lo;
                cvt_split(v.x, v.y, hi, lo);
                *(uint32_t*)(AsHi + row * LDA + c)     = hi;
                *(uint32_t*)(AsLo + row * LDA + c)     = lo;
                cvt_split(v.z, v.w, hi, lo);
                *(uint32_t*)(AsHi + row * LDA + c + 2) = hi;
                *(uint32_t*)(AsLo + row * LDA + c + 2) = lo;
            }
        } else {
            #pragma unroll
            for (int q = 0; q < 16; q++) {
                int c = sel * 64 + q * 4;
                *(uint32_t*)(AsHi + row * LDA + c)     = 0u;
                *(uint32_t*)(AsLo + row * LDA + c)     = 0u;
                *(uint32_t*)(AsHi + row * LDA + c + 2) = 0u;
                *(uint32_t*)(AsLo + row * LDA + c + 2) = 0u;
            }
        }
    }
    // Small params + coords + vid
    if (tid < 128) {
        sGa[tid] = gamma[tid];
        sBe[tid] = beta[tid];
        #pragma unroll
        for (int q = 0; q < 3; q++) sWp[q * 128 + tid] = Wp[q * 128 + tid];
        int gr = row0 + tid;
        int4 cd = (gr < N_PTS) ? *reinterpret_cast<const int4*>(&coords[(size_t)gr * 4])
                               : make_int4(0, 0, 0, 0);
        sCd[tid]  = cd;
        sVid[tid] = ((cd.w * GXD + (cd.x >> 3)) * GYD + (cd.y >> 3)) * GZD + (cd.z >> 3);
    }
    __syncthreads();

    // ---- Warp-tiled mainloop: warp w owns rows [w*16, w*16+16), all 128 cols ----
    const int w    = tid >> 5;
    const int lane = tid & 31;
    const int g    = lane >> 2;      // groupID
    const int t    = lane & 3;       // thread-in-group
    const int w16  = w * 16;

    float acc[16][4];
    #pragma unroll
    for (int nt = 0; nt < 16; nt++)
        #pragma unroll
        for (int j = 0; j < 4; j++) acc[nt][j] = 0.f;

    #pragma unroll 1
    for (int pass = 0; pass < 3; pass++) {
        const __half* Ap = (pass == 1) ? AsLo : AsHi;
        const __half* Bp = (pass == 2) ? BsLo : BsHi;
        #pragma unroll 1
        for (int k16 = 0; k16 < 8; k16++) {
            const int kk = k16 * 16 + 2 * t;
            uint32_t a0 = *(const uint32_t*)(Ap + (w16 + g)     * LDA + kk);
            uint32_t a1 = *(const uint32_t*)(Ap + (w16 + g + 8) * LDA + kk);
            uint32_t a2 = *(const uint32_t*)(Ap + (w16 + g)     * LDA + kk + 8);
            uint32_t a3 = *(const uint32_t*)(Ap + (w16 + g + 8) * LDA + kk + 8);
            #pragma unroll
            for (int nt = 0; nt < 16; nt++) {
                uint32_t b0 = *(const uint32_t*)(Bp + (nt * 8 + g) * LDA + kk);
                uint32_t b1 = *(const uint32_t*)(Bp + (nt * 8 + g) * LDA + kk + 8);
                mma16816(acc[nt], a0, a1, a2, a3, b0, b1);
            }
        }
    }
    __syncthreads();   // all warps done reading operands; Hs may overwrite them

    // ---- LayerNorm stats: rows r0 = w16+g, r1 = r0+8 ----
    float s0 = 0.f, q0 = 0.f, s1 = 0.f, q1 = 0.f;
    #pragma unroll
    for (int nt = 0; nt < 16; nt++) {
        s0 += acc[nt][0] + acc[nt][1];
        q0 += acc[nt][0] * acc[nt][0] + acc[nt][1] * acc[nt][1];
        s1 += acc[nt][2] + acc[nt][3];
        q1 += acc[nt][2] * acc[nt][2] + acc[nt][3] * acc[nt][3];
    }
    #pragma unroll
    for (int off = 1; off <= 2; off <<= 1) {
        s0 += __shfl_xor_sync(0xffffffffu, s0, off);
        q0 += __shfl_xor_sync(0xffffffffu, q0, off);
        s1 += __shfl_xor_sync(0xffffffffu, s1, off);
        q1 += __shfl_xor_sync(0xffffffffu, q1, off);
    }
    float mu0 = s0 * (1.f / 128.f), var0 = q0 * (1.f / 128.f) - mu0 * mu0;
    float mu1 = s1 * (1.f / 128.f), var1 = q1 * (1.f / 128.f) - mu1 * mu1;
    float rs0 = rsqrtf(var0 + 1e-6f);
    float rs1 = rsqrtf(var1 + 1e-6f);

    const int r0l = w16 + g, r1l = r0l + 8;
    int4 cd0 = sCd[r0l], cd1 = sCd[r1l];
    float fx0 = (float)cd0.x, fy0 = (float)cd0.y, fz0 = (float)cd0.z;
    float fx1 = (float)cd1.x, fy1 = (float)cd1.y, fz1 = (float)cd1.z;

    // ---- F = [h*cos | h*sin] into float4-rotated smem ----
    // channel c lives at Hs[p*256 + (((c>>2)+p)&63)*4 + (c&3)]
    #pragma unroll
    for (int nt = 0; nt < 16; nt++) {
        #pragma unroll
        for (int j = 0; j < 2; j++) {
            int c  = nt * 8 + 2 * t + j;       // cos channel index (0..127)
            int cs128 = c + 128;               // sin channel index
            float ga = sGa[c], be = sBe[c];
            float w0 = sWp[c], w1 = sWp[128 + c], w2 = sWp[256 + c];
            {
                float hn = (acc[nt][j] - mu0) * rs0 * ga + be;
                float sn, cs;
                sincos_red(fx0 * w0 + fy0 * w1 + fz0 * w2, &sn, &cs);
                Hs[r0l * 256 + ((((c >> 2) + r0l) & 63) << 2) + (c & 3)]           = hn * cs;
                Hs[r0l * 256 + ((((cs128 >> 2) + r0l) & 63) << 2) + (cs128 & 3)]   = hn * sn;
            }
            {
                float hn = (acc[nt][2 + j] - mu1) * rs1 * ga + be;
                float sn, cs;
                sincos_red(fx1 * w0 + fy1 * w1 + fz1 * w2, &sn, &cs);
                Hs[r1l * 256 + ((((c >> 2) + r1l) & 63) << 2) + (c & 3)]           = hn * cs;
                Hs[r1l * 256 + ((((cs128 >> 2) + r1l) & 63) << 2) + (cs128 & 3)]   = hn * sn;
            }
        }
    }
    // Count channel: one atomic per point
    if (tid < 128 && row0 + tid < N_PTS)
        atomicAdd(&g_cnt[sVid[tid]], 1.0f);

    __syncthreads();

    // ---- Vectorized scatter: warp per point, lane owns float4 groups c4 = lane, lane+32 ----
    for (int i = 0; i < 16; i++) {
        int p  = w * 16 + i;
        int gp = row0 + p;
        if (gp >= N_PTS) break;          // warp-uniform
        float* gc = g_grid + (size_t)sVid[p] * NFCH;
        float4 v0 = Hs4[p * 64 + ((lane + p) & 63)];
        float4 v1 = Hs4[p * 64 + ((lane + 32 + p) & 63)];
        red_add_v4(gc + 4 * lane,       v0);
        red_add_v4(gc + 128 + 4 * lane, v1);
    }
}

// ---------------------------------------------------------------------------
// K2a: 9-point box sum over (y,z), float4 channels. 4 cells per 256-thr block.
// ---------------------------------------------------------------------------
__global__ void k_box_yz() {
    int cell = blockIdx.x * 4 + (threadIdx.x >> 6);
    int ch4  = threadIdx.x & 63;
    int rem  = cell % (GYD * GZD);
    int cy   = rem / GZD;
    int cz   = rem % GZD;
    int dylo = (cy > 0) ? -1 : 0, dyhi = (cy < GYD - 1) ? 1 : 0;
    int dzlo = (cz > 0) ? -1 : 0, dzhi = (cz < GZD - 1) ? 1 : 0;

    const float4* grid4 = (const float4*)g_grid;
    float4 s = make_float4(0.f, 0.f, 0.f, 0.f);
    float  sc = 0.f;
    for (int dy = dylo; dy <= dyhi; dy++)
        for (int dz = dzlo; dz <= dzhi; dz++) {
            int nb = cell + dy * GZD + dz;
            float4 v = grid4[(size_t)nb * 64 + ch4];
            s.x += v.x; s.y += v.y; s.z += v.z; s.w += v.w;
            if (ch4 == 0) sc += g_cnt[nb];
        }
    ((float4*)g_tmp)[(size_t)cell * 64 + ch4] = s;
    if (ch4 == 0) g_tmpc[cell] = sc;
}

// ---------------------------------------------------------------------------
// K2b: 3-point sum over x + divide by count. 4 cells per 256-thread block.
// ---------------------------------------------------------------------------
__global__ void k_box_x_div() {
    int cell = blockIdx.x * 4 + (threadIdx.x >> 6);
    int ch4  = threadIdx.x & 63;
    int cx   = (cell % (GXD * GYD * GZD)) / (GYD * GZD);

    const float4* tmp4 = (const float4*)g_tmp;
    float4 num = make_float4(0.f, 0.f, 0.f, 0.f);
    float  den = 0.f;
    #pragma unroll
    for (int dx = -1; dx <= 1; dx++) {
        int xx = cx + dx;
        if (xx < 0 || xx >= GXD) continue;
        int nb = cell + dx * GYD * GZD;
        float4 v = tmp4[(size_t)nb * 64 + ch4];
        num.x += v.x; num.y += v.y; num.z += v.z; num.w += v.w;
        den += g_tmpc[nb];
    }
    float inv = 1.0f / fmaxf(den, 1e-12f);
    float4 r = make_float4(num.x * inv, num.y * inv, num.z * inv, num.w * inv);
    ((float4*)g_agg)[(size_t)cell * 64 + ch4] = r;
}

// ---------------------------------------------------------------------------
// K3: gather + recombine, float4: warp per point, lane = float4 group (c4g)
// out[i][4c..4c+3] = agg[vid][c4g]*cos4 + agg[vid][32+c4g]*sin4
// ---------------------------------------------------------------------------
__global__ void k_gather(const int* __restrict__ coords,
                         const float* __restrict__ Wp,
                         float* __restrict__ out)
{
    int tIdx = blockIdx.x * blockDim.x + threadIdx.x;
    int i    = tIdx >> 5;          // point
    int c4g  = tIdx & 31;          // float4 group within 128 channels
    if (i >= N_PTS) return;

    int4 cd = *reinterpret_cast<const int4*>(&coords[(size_t)i * 4]);
    int vid = ((cd.w * GXD + (cd.x >> 3)) * GYD + (cd.y >> 3)) * GZD + (cd.z >> 3);
    float fx = (float)cd.x, fy = (float)cd.y, fz = (float)cd.z;

    const float4* Wp4 = (const float4*)Wp;
    float4 w0 = Wp4[c4g];
    float4 w1 = Wp4[32 + c4g];
    float4 w2 = Wp4[64 + c4g];

    const float4* a = (const float4*)g_agg + (size_t)vid * 64;
    float4 ac = a[c4g];
    float4 as = a[32 + c4g];

    float4 o;
    float sn, cs;
    sincos_red(fx * w0.x + fy * w1.x + fz * w2.x, &sn, &cs);
    o.x = ac.x * cs + as.x * sn;
    sincos_red(fx * w0.y + fy * w1.y + fz * w2.y, &sn, &cs);
    o.y = ac.y * cs + as.y * sn;
    sincos_red(fx * w0.z + fy * w1.z + fz * w2.z, &sn, &cs);
    o.z = ac.z * cs + as.z * sn;
    sincos_red(fx * w0.w + fy * w1.w + fz * w2.w, &sn, &cs);
    o.w = ac.w * cs + as.w * sn;

    ((float4*)out)[(size_t)i * 32 + c4g] = o;
}

// ---------------------------------------------------------------------------
// Launch
// ---------------------------------------------------------------------------
extern "C" void kernel_launch(void* const* d_in, const int* in_sizes, int n_in,
                              void* d_out, int out_size)
{
    const float* x      = (const float*)d_in[0];
    const int*   coords = (const int*)  d_in[1];
    const float* Wm     = (const float*)d_in[2];
    const float* gamma  = (const float*)d_in[3];
    const float* beta   = (const float*)d_in[4];
    const float* Wp     = (const float*)d_in[5];
    float* out = (float*)d_out;

    cudaFuncSetAttribute(k_gemm_ln_scatter,
                         cudaFuncAttributeMaxDynamicSharedMemorySize, SMEM_BYTES);

    k_zero<<<((NCELLS * NFCH) / 4 + 255) / 256, 256>>>();
    k_gemm_ln_scatter<<<(N_PTS + 127) / 128, 256, SMEM_BYTES>>>(
        x, coords, Wm, gamma, beta, Wp);
    k_box_yz<<<NCELLS / 4, 256>>>();
    k_box_x_div<<<NCELLS / 4, 256>>>();
    k_gather<<<(N_PTS * 32 + 255) / 256, 256>>>(coords, Wp, out);
}

// round 6
// speedup vs baseline: 2.2349x; 1.0805x over previous
#include <cuda_runtime.h>
#include <cuda_fp16.h>
#include <cstdint>

// Problem constants (fixed by the dataset)
#define N_PTS   300000
#define INC     128
#define BATCH   4
#define GXD     50
#define GYD     50
#define GZD     4
#define NCELLS  40000          // BATCH*GXD*GYD*GZD
#define NFCH    256            // 2*INC feature channels (cos | sin)

// Scratch (static device globals — no allocation allowed)
__device__ float g_grid[NCELLS * NFCH];     // scatter target [cell][256]
__device__ float g_cnt [NCELLS];            // per-cell point count
__device__ float g_tmp [NCELLS * NFCH];     // y/z box-summed features
__device__ float g_tmpc[NCELLS];            // y/z box-summed counts
__device__ float g_agg [NCELLS * NFCH];     // final per-cell averages

// sin/cos: explicit range reduction into [-pi, pi], then HW MUFU intrinsics.
__device__ __forceinline__ void sincos_red(float x, float* s, float* c) {
    float r = x - 6.283185307179586f * rintf(x * 0.15915494309189535f);
    *s = __sinf(r);
    *c = __cosf(r);
}

// Vectorized float4 reduction (PTX ISA 8.1, sm_90+ base feature)
__device__ __forceinline__ void red_add_v4(float* p, float4 v) {
    asm volatile("red.global.add.v4.f32 [%0], {%1, %2, %3, %4};"
                 :: "l"(p), "f"(v.x), "f"(v.y), "f"(v.z), "f"(v.w) : "memory");
}

// ---------------------------------------------------------------------------
// K0: zero the scatter grid + counts
// ---------------------------------------------------------------------------
__global__ void k_zero() {
    int i = blockIdx.x * blockDim.x + threadIdx.x;
    float4 z = make_float4(0.f, 0.f, 0.f, 0.f);
    if (i < (NCELLS * NFCH) / 4) reinterpret_cast<float4*>(g_grid)[i] = z;
    if (i < NCELLS / 4)          reinterpret_cast<float4*>(g_cnt)[i]  = z;
}

// ---------------------------------------------------------------------------
// K1: mma.sync fp16x3-split GEMM (h = x @ Wm^T) + per-row LayerNorm +
//     sincos + float4 vectorized atomic scatter.
//     512 threads (16 warps), 128 points/block. Warp = (row16-group, col-half):
//     wr = w>>1 owns rows [wr*16, wr*16+16), nh = w&1 owns cols [nh*64, nh*64+64).
// ---------------------------------------------------------------------------
#define LDA   136                       // halves per smem row (8-half pad)
#define TILE_HALF_BYTES (128 * LDA * 2) // 34816 B per fp16 tile

#define OFF_A_HI  0
#define OFF_A_LO  (OFF_A_HI + TILE_HALF_BYTES)
#define OFF_B_HI  (OFF_A_LO + TILE_HALF_BYTES)
#define OFF_B_LO  (OFF_B_HI + TILE_HALF_BYTES)   // operands end at 139264
#define OFF_COORD (OFF_B_LO + TILE_HALF_BYTES)   // int4[128]  = 2048
#define OFF_VID   (OFF_COORD + 2048)             // int[128]   = 512
#define OFF_GAMMA (OFF_VID + 512)
#define OFF_BETA  (OFF_GAMMA + 512)
#define OFF_WP    (OFF_BETA + 512)               // float[384] = 1536
#define OFF_PS    (OFF_WP + 1536)                // float[128][2] s + [128][2] q = 2048
#define SMEM_BYTES (OFF_PS + 2048)               // 146432

// F staging (reuses operand region after mainloop):
// Hs4[p][phys4], phys4 = (c4 + p) & 63  (float4-granular rotation, p = 0..127)
#define OFF_HS    0                              // 128*64*16 = 131072 <= 139264

__device__ __forceinline__ void mma16816(float* c,
                                         uint32_t a0, uint32_t a1,
                                         uint32_t a2, uint32_t a3,
                                         uint32_t b0, uint32_t b1) {
    asm volatile(
        "mma.sync.aligned.m16n8k16.row.col.f32.f16.f16.f32 "
        "{%0,%1,%2,%3}, {%4,%5,%6,%7}, {%8,%9}, {%0,%1,%2,%3};"
        : "+f"(c[0]), "+f"(c[1]), "+f"(c[2]), "+f"(c[3])
        : "r"(a0), "r"(a1), "r"(a2), "r"(a3), "r"(b0), "r"(b1));
}

// split (v0,v1) into packed half2 hi + half2 lo
__device__ __forceinline__ void cvt_split(float v0, float v1,
                                          uint32_t& hi, uint32_t& lo) {
    __half h0 = __float2half_rn(v0);
    __half h1 = __float2half_rn(v1);
    __half l0 = __float2half_rn(v0 - __half2float(h0));
    __half l1 = __float2half_rn(v1 - __half2float(h1));
    hi = ((uint32_t)__half_as_ushort(h1) << 16) | __half_as_ushort(h0);
    lo = ((uint32_t)__half_as_ushort(l1) << 16) | __half_as_ushort(l0);
}

__global__ void __launch_bounds__(512)
k_gemm_ln_scatter(const float* __restrict__ x,
                  const int*   __restrict__ coords,
                  const float* __restrict__ Wm,
                  const float* __restrict__ gamma,
                  const float* __restrict__ beta,
                  const float* __restrict__ Wp)
{
    extern __shared__ char smraw[];
    __half* AsHi = (__half*)(smraw + OFF_A_HI);
    __half* AsLo = (__half*)(smraw + OFF_A_LO);
    __half* BsHi = (__half*)(smraw + OFF_B_HI);
    __half* BsLo = (__half*)(smraw + OFF_B_LO);
    int4*   sCd  = (int4*)  (smraw + OFF_COORD);
    int*    sVid = (int*)   (smraw + OFF_VID);
    float*  sGa  = (float*) (smraw + OFF_GAMMA);
    float*  sBe  = (float*) (smraw + OFF_BETA);
    float*  sWp  = (float*) (smraw + OFF_WP);
    float*  sPS  = (float*) (smraw + OFF_PS);        // [128][2] sums
    float*  sPQ  = (float*) (smraw + OFF_PS + 1024); // [128][2] sqsums
    float*  Hs   = (float*) (smraw + OFF_HS);
    float4* Hs4  = (float4*)(smraw + OFF_HS);

    const int tid  = threadIdx.x;
    const int row0 = blockIdx.x * 128;

    // ---- Stage operands: 4 threads per row, each does 32 cols (8 float4) ----
    {
        int row = tid >> 2, sel = tid & 3;
        const float4* wrow = (const float4*)(Wm + (size_t)row * 128) + sel * 8;
        #pragma unroll
        for (int q = 0; q < 8; q++) {
            float4 v = wrow[q];
            int c = sel * 32 + q * 4;
            uint32_t hi, lo;
            cvt_split(v.x, v.y, hi, lo);
            *(uint32_t*)(BsHi + row * LDA + c)     = hi;
            *(uint32_t*)(BsLo + row * LDA + c)     = lo;
            cvt_split(v.z, v.w, hi, lo);
            *(uint32_t*)(BsHi + row * LDA + c + 2) = hi;
            *(uint32_t*)(BsLo + row * LDA + c + 2) = lo;
        }
        int gr = row0 + row;
        if (gr < N_PTS) {
            const float4* xrow = (const float4*)(x + (size_t)gr * 128) + sel * 8;
            #pragma unroll
            for (int q = 0; q < 8; q++) {
                float4 v = xrow[q];
                int c = sel * 32 + q * 4;
                uint32_t hi, lo;
                cvt_split(v.x, v.y, hi, lo);
                *(uint32_t*)(AsHi + row * LDA + c)     = hi;
                *(uint32_t*)(AsLo + row * LDA + c)     = lo;
                cvt_split(v.z, v.w, hi, lo);
                *(uint32_t*)(AsHi + row * LDA + c + 2) = hi;
                *(uint32_t*)(AsLo + row * LDA + c + 2) = lo;
            }
        } else {
            #pragma unroll
            for (int q = 0; q < 8; q++) {
                int c = sel * 32 + q * 4;
                *(uint32_t*)(AsHi + row * LDA + c)     = 0u;
                *(uint32_t*)(AsLo + row * LDA + c)     = 0u;
                *(uint32_t*)(AsHi + row * LDA + c + 2) = 0u;
                *(uint32_t*)(AsLo + row * LDA + c + 2) = 0u;
            }
        }
    }
    // Small params + coords + vid
    if (tid < 128) {
        sGa[tid] = gamma[tid];
        sBe[tid] = beta[tid];
        #pragma unroll
        for (int q = 0; q < 3; q++) sWp[q * 128 + tid] = Wp[q * 128 + tid];
        int gr = row0 + tid;
        int4 cd = (gr < N_PTS) ? *reinterpret_cast<const int4*>(&coords[(size_t)gr * 4])
                               : make_int4(0, 0, 0, 0);
        sCd[tid]  = cd;
        sVid[tid] = ((cd.w * GXD + (cd.x >> 3)) * GYD + (cd.y >> 3)) * GZD + (cd.z >> 3);
    }
    __syncthreads();

    // ---- Warp-tiled mainloop ----
    const int w    = tid >> 5;       // 0..15
    const int lane = tid & 31;
    const int g    = lane >> 2;      // groupID
    const int t    = lane & 3;       // thread-in-group
    const int wr   = w >> 1;         // row group 0..7
    const int nh   = w & 1;          // col half 0..1
    const int w16  = wr * 16;
    const int nb0  = nh * 8;         // first n-tile index (n-tiles of 8 cols)

    float acc[8][4];
    #pragma unroll
    for (int nt = 0; nt < 8; nt++)
        #pragma unroll
        for (int j = 0; j < 4; j++) acc[nt][j] = 0.f;

    #pragma unroll 1
    for (int pass = 0; pass < 3; pass++) {
        const __half* Ap = (pass == 1) ? AsLo : AsHi;
        const __half* Bp = (pass == 2) ? BsLo : BsHi;
        #pragma unroll 2
        for (int k16 = 0; k16 < 8; k16++) {
            const int kk = k16 * 16 + 2 * t;
            uint32_t a0 = *(const uint32_t*)(Ap + (w16 + g)     * LDA + kk);
            uint32_t a1 = *(const uint32_t*)(Ap + (w16 + g + 8) * LDA + kk);
            uint32_t a2 = *(const uint32_t*)(Ap + (w16 + g)     * LDA + kk + 8);
            uint32_t a3 = *(const uint32_t*)(Ap + (w16 + g + 8) * LDA + kk + 8);
            #pragma unroll
            for (int nt = 0; nt < 8; nt++) {
                uint32_t b0 = *(const uint32_t*)(Bp + ((nb0 + nt) * 8 + g) * LDA + kk);
                uint32_t b1 = *(const uint32_t*)(Bp + ((nb0 + nt) * 8 + g) * LDA + kk + 8);
                mma16816(acc[nt], a0, a1, a2, a3, b0, b1);
            }
        }
    }
    __syncthreads();   // all warps done reading operands; Hs may overwrite them

    // ---- LayerNorm stats: partial (64-col) sums, combine across col halves ----
    float s0 = 0.f, q0 = 0.f, s1 = 0.f, q1 = 0.f;
    #pragma unroll
    for (int nt = 0; nt < 8; nt++) {
        s0 += acc[nt][0] + acc[nt][1];
        q0 += acc[nt][0] * acc[nt][0] + acc[nt][1] * acc[nt][1];
        s1 += acc[nt][2] + acc[nt][3];
        q1 += acc[nt][2] * acc[nt][2] + acc[nt][3] * acc[nt][3];
    }
    #pragma unroll
    for (int off = 1; off <= 2; off <<= 1) {
        s0 += __shfl_xor_sync(0xffffffffu, s0, off);
        q0 += __shfl_xor_sync(0xffffffffu, q0, off);
        s1 += __shfl_xor_sync(0xffffffffu, s1, off);
        q1 += __shfl_xor_sync(0xffffffffu, q1, off);
    }
    const int r0l = w16 + g, r1l = r0l + 8;
    if (t == 0) {
        sPS[r0l * 2 + nh] = s0;  sPQ[r0l * 2 + nh] = q0;
        sPS[r1l * 2 + nh] = s1;  sPQ[r1l * 2 + nh] = q1;
    }
    __syncthreads();
    {
        float fs0 = sPS[r0l * 2] + sPS[r0l * 2 + 1];
        float fq0 = sPQ[r0l * 2] + sPQ[r0l * 2 + 1];
        float fs1 = sPS[r1l * 2] + sPS[r1l * 2 + 1];
        float fq1 = sPQ[r1l * 2] + sPQ[r1l * 2 + 1];
        s0 = fs0; q0 = fq0; s1 = fs1; q1 = fq1;
    }
    float mu0 = s0 * (1.f / 128.f), var0 = q0 * (1.f / 128.f) - mu0 * mu0;
    float mu1 = s1 * (1.f / 128.f), var1 = q1 * (1.f / 128.f) - mu1 * mu1;
    float rs0 = rsqrtf(var0 + 1e-6f);
    float rs1 = rsqrtf(var1 + 1e-6f);

    int4 cd0 = sCd[r0l], cd1 = sCd[r1l];
    float fx0 = (float)cd0.x, fy0 = (float)cd0.y, fz0 = (float)cd0.z;
    float fx1 = (float)cd1.x, fy1 = (float)cd1.y, fz1 = (float)cd1.z;

    // ---- F = [h*cos | h*sin] into float4-rotated smem ----
    // channel c lives at Hs[p*256 + (((c>>2)+p)&63)*4 + (c&3)]
    #pragma unroll
    for (int nt = 0; nt < 8; nt++) {
        #pragma unroll
        for (int j = 0; j < 2; j++) {
            int c  = (nb0 + nt) * 8 + 2 * t + j;   // cos channel index (0..127)
            int cs128 = c + 128;                   // sin channel index
            float ga = sGa[c], be = sBe[c];
            float w0 = sWp[c], w1 = sWp[128 + c], w2 = sWp[256 + c];
            {
                float hn = (acc[nt][j] - mu0) * rs0 * ga + be;
                float sn, cs;
                sincos_red(fx0 * w0 + fy0 * w1 + fz0 * w2, &sn, &cs);
                Hs[r0l * 256 + ((((c >> 2) + r0l) & 63) << 2) + (c & 3)]           = hn * cs;
                Hs[r0l * 256 + ((((cs128 >> 2) + r0l) & 63) << 2) + (cs128 & 3)]   = hn * sn;
            }
            {
                float hn = (acc[nt][2 + j] - mu1) * rs1 * ga + be;
                float sn, cs;
                sincos_red(fx1 * w0 + fy1 * w1 + fz1 * w2, &sn, &cs);
                Hs[r1l * 256 + ((((c >> 2) + r1l) & 63) << 2) + (c & 3)]           = hn * cs;
                Hs[r1l * 256 + ((((cs128 >> 2) + r1l) & 63) << 2) + (cs128 & 3)]   = hn * sn;
            }
        }
    }
    // Count channel: one atomic per point
    if (tid < 128 && row0 + tid < N_PTS)
        atomicAdd(&g_cnt[sVid[tid]], 1.0f);

    __syncthreads();

    // ---- Vectorized scatter: warp per point (8 points/warp), lane owns
    //      float4 groups c4 = lane and lane+32 ----
    for (int i = 0; i < 8; i++) {
        int p  = w * 8 + i;
        int gp = row0 + p;
        if (gp >= N_PTS) break;          // warp-uniform
        float* gc = g_grid + (size_t)sVid[p] * NFCH;
        float4 v0 = Hs4[p * 64 + ((lane + p) & 63)];
        float4 v1 = Hs4[p * 64 + ((lane + 32 + p) & 63)];
        red_add_v4(gc + 4 * lane,       v0);
        red_add_v4(gc + 128 + 4 * lane, v1);
    }
}

// ---------------------------------------------------------------------------
// K2a: 9-point box sum over (y,z), float4 channels. 4 cells per 256-thr block.
// ---------------------------------------------------------------------------
__global__ void k_box_yz() {
    int cell = blockIdx.x * 4 + (threadIdx.x >> 6);
    int ch4  = threadIdx.x & 63;
    int rem  = cell % (GYD * GZD);
    int cy   = rem / GZD;
    int cz   = rem % GZD;
    int dylo = (cy > 0) ? -1 : 0, dyhi = (cy < GYD - 1) ? 1 : 0;
    int dzlo = (cz > 0) ? -1 : 0, dzhi = (cz < GZD - 1) ? 1 : 0;

    const float4* grid4 = (const float4*)g_grid;
    float4 s = make_float4(0.f, 0.f, 0.f, 0.f);
    float  sc = 0.f;
    for (int dy = dylo; dy <= dyhi; dy++)
        for (int dz = dzlo; dz <= dzhi; dz++) {
            int nb = cell + dy * GZD + dz;
            float4 v = grid4[(size_t)nb * 64 + ch4];
            s.x += v.x; s.y += v.y; s.z += v.z; s.w += v.w;
            if (ch4 == 0) sc += g_cnt[nb];
        }
    ((float4*)g_tmp)[(size_t)cell * 64 + ch4] = s;
    if (ch4 == 0) g_tmpc[cell] = sc;
}

// ---------------------------------------------------------------------------
// K2b: 3-point sum over x + divide by count. 4 cells per 256-thread block.
// ---------------------------------------------------------------------------
__global__ void k_box_x_div() {
    int cell = blockIdx.x * 4 + (threadIdx.x >> 6);
    int ch4  = threadIdx.x & 63;
    int cx   = (cell % (GXD * GYD * GZD)) / (GYD * GZD);

    const float4* tmp4 = (const float4*)g_tmp;
    float4 num = make_float4(0.f, 0.f, 0.f, 0.f);
    float  den = 0.f;
    #pragma unroll
    for (int dx = -1; dx <= 1; dx++) {
        int xx = cx + dx;
        if (xx < 0 || xx >= GXD) continue;
        int nb = cell + dx * GYD * GZD;
        float4 v = tmp4[(size_t)nb * 64 + ch4];
        num.x += v.x; num.y += v.y; num.z += v.z; num.w += v.w;
        den += g_tmpc[nb];
    }
    float inv = 1.0f / fmaxf(den, 1e-12f);
    float4 r = make_float4(num.x * inv, num.y * inv, num.z * inv, num.w * inv);
    ((float4*)g_agg)[(size_t)cell * 64 + ch4] = r;
}

// ---------------------------------------------------------------------------
// K3: gather + recombine, float4: warp per point, lane = float4 group (c4g)
// ---------------------------------------------------------------------------
__global__ void k_gather(const int* __restrict__ coords,
                         const float* __restrict__ Wp,
                         float* __restrict__ out)
{
    int tIdx = blockIdx.x * blockDim.x + threadIdx.x;
    int i    = tIdx >> 5;          // point
    int c4g  = tIdx & 31;          // float4 group within 128 channels
    if (i >= N_PTS) return;

    int4 cd = *reinterpret_cast<const int4*>(&coords[(size_t)i * 4]);
    int vid = ((cd.w * GXD + (cd.x >> 3)) * GYD + (cd.y >> 3)) * GZD + (cd.z >> 3);
    float fx = (float)cd.x, fy = (float)cd.y, fz = (float)cd.z;

    const float4* Wp4 = (const float4*)Wp;
    float4 w0 = Wp4[c4g];
    float4 w1 = Wp4[32 + c4g];
    float4 w2 = Wp4[64 + c4g];

    const float4* a = (const float4*)g_agg + (size_t)vid * 64;
    float4 ac = a[c4g];
    float4 as = a[32 + c4g];

    float4 o;
    float sn, cs;
    sincos_red(fx * w0.x + fy * w1.x + fz * w2.x, &sn, &cs);
    o.x = ac.x * cs + as.x * sn;
    sincos_red(fx * w0.y + fy * w1.y + fz * w2.y, &sn, &cs);
    o.y = ac.y * cs + as.y * sn;
    sincos_red(fx * w0.z + fy * w1.z + fz * w2.z, &sn, &cs);
    o.z = ac.z * cs + as.z * sn;
    sincos_red(fx * w0.w + fy * w1.w + fz * w2.w, &sn, &cs);
    o.w = ac.w * cs + as.w * sn;

    ((float4*)out)[(size_t)i * 32 + c4g] = o;
}

// ---------------------------------------------------------------------------
// Launch
// ---------------------------------------------------------------------------
extern "C" void kernel_launch(void* const* d_in, const int* in_sizes, int n_in,
                              void* d_out, int out_size)
{
    const float* x      = (const float*)d_in[0];
    const int*   coords = (const int*)  d_in[1];
    const float* Wm     = (const float*)d_in[2];
    const float* gamma  = (const float*)d_in[3];
    const float* beta   = (const float*)d_in[4];
    const float* Wp     = (const float*)d_in[5];
    float* out = (float*)d_out;

    cudaFuncSetAttribute(k_gemm_ln_scatter,
                         cudaFuncAttributeMaxDynamicSharedMemorySize, SMEM_BYTES);

    k_zero<<<((NCELLS * NFCH) / 4 + 255) / 256, 256>>>();
    k_gemm_ln_scatter<<<(N_PTS + 127) / 128, 512, SMEM_BYTES>>>(
        x, coords, Wm, gamma, beta, Wp);
    k_box_yz<<<NCELLS / 4, 256>>>();
    k_box_x_div<<<NCELLS / 4, 256>>>();
    k_gather<<<(N_PTS * 32 + 255) / 256, 256>>>(coords, Wp, out);
}